// round 7
// baseline (speedup 1.0000x reference)
#include <cuda_runtime.h>
#include <mma.h>
#include <cstddef>
#include <cstdint>

using namespace nvcuda;

#define NN 100000
#define NN_PAD 100096            // 782 * 128
#define NE 1600000
#define SCAN_B 1024
#define NBLK ((NN + SCAN_B - 1) / SCAN_B)   // 98

// ---------------- scratch ---------------------------------------------------
__device__ float g_x[(size_t)NN_PAD * 128];  // tf32-rounded input x (padded)
__device__ float g_yz[(size_t)NN_PAD * 256];
__device__ float g_h[(size_t)NN_PAD * 128];  // tf32-rounded activations (padded)
__device__ float g_wcat[256 * 128];          // tf32-rounded [Wl ; Wr]
__device__ int   g_cnt[NN];
__device__ int   g_offs[NN + 1];
__device__ int   g_cursor[NN];
__device__ int   g_csrc[NE];
__device__ int   g_bsum[NBLK];

// ---------------- helpers ---------------------------------------------------
__device__ __forceinline__ float4 round_tf32_4(float4 v) {
    return make_float4(wmma::__float_to_tf32(v.x), wmma::__float_to_tf32(v.y),
                       wmma::__float_to_tf32(v.z), wmma::__float_to_tf32(v.w));
}
__device__ __forceinline__ uint32_t smem_u32(const void* p) {
    return (uint32_t)__cvta_generic_to_shared(p);
}
#define CPA(dst, src) \
    asm volatile("cp.async.cg.shared.global [%0], [%1], 16;" :: "r"(dst), "l"(src))
#define CPC() asm volatile("cp.async.commit_group;")
#define CPW(n) asm volatile("cp.async.wait_group %0;" :: "n"(n))

// ---------------- CSR build -------------------------------------------------
__global__ void count_deg(const int* __restrict__ dst, int* __restrict__ cnt) {
    int e = blockIdx.x * blockDim.x + threadIdx.x;
    if (e < NE) atomicAdd(cnt + dst[e], 1);
}
__global__ void zero_cnt(int* __restrict__ cnt) {
    int i = blockIdx.x * blockDim.x + threadIdx.x;
    if (i < NN) cnt[i] = 0;
}
__global__ void scan_a(const int* __restrict__ cnt, int* __restrict__ offs,
                       int* __restrict__ bsum) {
    __shared__ int sh[SCAN_B];
    int gid = blockIdx.x * SCAN_B + threadIdx.x;
    int v = (gid < NN) ? cnt[gid] : 0;
    sh[threadIdx.x] = v;
    __syncthreads();
    for (int d = 1; d < SCAN_B; d <<= 1) {
        int t = (threadIdx.x >= d) ? sh[threadIdx.x - d] : 0;
        __syncthreads();
        sh[threadIdx.x] += t;
        __syncthreads();
    }
    if (gid < NN) offs[gid] = sh[threadIdx.x] - v;
    if (threadIdx.x == SCAN_B - 1) bsum[blockIdx.x] = sh[threadIdx.x];
}
__global__ void scan_b(int* __restrict__ bsum) {
    __shared__ int sh[128];
    int v = (threadIdx.x < NBLK) ? bsum[threadIdx.x] : 0;
    sh[threadIdx.x] = v;
    __syncthreads();
    for (int d = 1; d < 128; d <<= 1) {
        int t = (threadIdx.x >= d) ? sh[threadIdx.x - d] : 0;
        __syncthreads();
        sh[threadIdx.x] += t;
        __syncthreads();
    }
    if (threadIdx.x < NBLK) bsum[threadIdx.x] = sh[threadIdx.x] - v;
}
__global__ void scan_c(int* __restrict__ offs, const int* __restrict__ bsum,
                       int* __restrict__ cursor) {
    int gid = blockIdx.x * blockDim.x + threadIdx.x;
    if (gid < NN) {
        int o = offs[gid] + bsum[gid >> 10];
        offs[gid] = o;
        cursor[gid] = o;
    }
    if (gid == 0) offs[NN] = NE;
}
__global__ void place_edges(const int* __restrict__ src, const int* __restrict__ dst,
                            int* __restrict__ cursor, int* __restrict__ csrc) {
    int e = blockIdx.x * blockDim.x + threadIdx.x;
    if (e < NE) {
        int p = atomicAdd(cursor + dst[e], 1);
        csrc[p] = src[e];
    }
}

// ---------------- tf32 pre-rounding ----------------------------------------
__global__ void cvt_x(const float4* __restrict__ in, float4* __restrict__ out) {
    int i = blockIdx.x * blockDim.x + threadIdx.x;
    if (i >= NN_PAD * 32) return;
    float4 v = (i < NN * 32) ? in[i] : make_float4(0.f, 0.f, 0.f, 0.f);
    out[i] = round_tf32_4(v);
}
__global__ void cvt_w(const float4* __restrict__ Wl, const float4* __restrict__ Wr,
                      float4* __restrict__ out, int n4half) {
    int i = blockIdx.x * blockDim.x + threadIdx.x;
    if (i < n4half) out[i] = round_tf32_4(Wl[i]);
    else if (i < 2 * n4half) out[i] = round_tf32_4(Wr[i - n4half]);
}

// ---------------- TF32 tensor-core GEMM ------------------------------------
// C[NN_PAD, N] = A[NN_PAD,128] * B[N,128]^T. A,B pre-rounded to tf32, padded.
// Block 128x128, BK=8, 8 warps (4x2), warp tile 32x64.
// 3-stage cp.async pipeline, 2-deep prefetch, ONE barrier per k-iter.
#define LDT 12

__global__ __launch_bounds__(256, 2) void tf32gemm(
    const float* __restrict__ A, const float* __restrict__ B,
    float* __restrict__ C, int N) {
    __shared__ float As[3][128][LDT];
    __shared__ float Bs[3][128][LDT];

    const int tid = threadIdx.x;
    const int warp = tid >> 5;
    const int wm = warp & 3;      // m offset 32*wm
    const int wn = warp >> 2;     // n offset 64*wn
    const int bm0 = blockIdx.y * 128;
    const int bn0 = blockIdx.x * 128;

    wmma::fragment<wmma::accumulator, 16, 16, 8, float> acc[2][4];
    #pragma unroll
    for (int i = 0; i < 2; i++)
        #pragma unroll
        for (int j = 0; j < 4; j++)
            wmma::fill_fragment(acc[i][j], 0.0f);

    // Loaders: per stage A,B each 128x8 floats = 256 float4; 1+1 per thread.
    const int r = tid >> 1;
    const int c = (tid & 1) * 4;
    const float* Ap = A + (size_t)(bm0 + r) * 128 + c;
    const float* Bp = B + (size_t)(bn0 + r) * 128 + c;

    const uint32_t sA = smem_u32(&As[0][r][c]);
    const uint32_t sB = smem_u32(&Bs[0][r][c]);
    const uint32_t STG = 128 * LDT * 4;   // stage stride in bytes

    // Prologue: prefetch stages 0 and 1 (groups 0, 1).
    CPA(sA, Ap); CPA(sB, Bp); CPC();
    CPA(sA + STG, Ap + 8); CPA(sB + STG, Bp + 8); CPC();

    #pragma unroll
    for (int t = 0; t < 16; t++) {
        if (t < 15) { CPW(1); } else { CPW(0); }
        __syncthreads();   // group t visible to all; stage (t+2)%3 free to write
        if (t < 14) {
            const uint32_t so = (uint32_t)((t + 2) % 3) * STG;
            const int k0 = (t + 2) * 8;
            CPA(sA + so, Ap + k0);
            CPA(sB + so, Bp + k0);
            CPC();
        }
        const int st = t % 3;
        wmma::fragment<wmma::matrix_a, 16, 16, 8, wmma::precision::tf32,
                       wmma::row_major> af[2];
        wmma::fragment<wmma::matrix_b, 16, 16, 8, wmma::precision::tf32,
                       wmma::col_major> bf[4];
        wmma::load_matrix_sync(af[0], &As[st][wm * 32 + 0][0], LDT);
        wmma::load_matrix_sync(af[1], &As[st][wm * 32 + 16][0], LDT);
        #pragma unroll
        for (int j = 0; j < 4; j++)
            wmma::load_matrix_sync(bf[j], &Bs[st][wn * 64 + j * 16][0], LDT);
        #pragma unroll
        for (int i = 0; i < 2; i++)
            #pragma unroll
            for (int j = 0; j < 4; j++)
                wmma::mma_sync(acc[i][j], af[i], bf[j], acc[i][j]);
    }

    #pragma unroll
    for (int i = 0; i < 2; i++)
        #pragma unroll
        for (int j = 0; j < 4; j++) {
            int row0 = bm0 + wm * 32 + i * 16;
            int col0 = bn0 + wn * 64 + j * 16;
            wmma::store_matrix_sync(C + (size_t)row0 * N + col0, acc[i][j], N,
                                    wmma::mem_row_major);
        }
}

// ---------------- fused aggregate + combine ---------------------------------
// out = [relu]( mean_{j in CSR[i]} y_j + z_i + b ). When RELU (layers 0/1):
// output is tf32-rounded (feeds next GEMM) and pad rows [NN,NN_PAD) are zeroed.
template <int C4, bool RELU>
__global__ void agg_combine(const float4* __restrict__ yz,
                            const int* __restrict__ csrc,
                            const int* __restrict__ offs,
                            const float* __restrict__ b,
                            float4* __restrict__ out) {
    const int S4 = 2 * C4;
    int gid = blockIdx.x * blockDim.x + threadIdx.x;
    int node = gid / C4;
    int lane = gid % C4;
    if (RELU) {
        if (node >= NN_PAD) return;
        if (node >= NN) {
            out[(size_t)node * C4 + lane] = make_float4(0.f, 0.f, 0.f, 0.f);
            return;
        }
    } else {
        if (node >= NN) return;
    }

    int s = offs[node], e = offs[node + 1];
    float4 acc = make_float4(0.f, 0.f, 0.f, 0.f);
    int i = s;
    for (; i + 3 < e; i += 4) {
        int s0 = csrc[i], s1 = csrc[i + 1], s2 = csrc[i + 2], s3 = csrc[i + 3];
        float4 v0 = yz[(size_t)s0 * S4 + lane];
        float4 v1 = yz[(size_t)s1 * S4 + lane];
        float4 v2 = yz[(size_t)s2 * S4 + lane];
        float4 v3 = yz[(size_t)s3 * S4 + lane];
        acc.x += (v0.x + v1.x) + (v2.x + v3.x);
        acc.y += (v0.y + v1.y) + (v2.y + v3.y);
        acc.z += (v0.z + v1.z) + (v2.z + v3.z);
        acc.w += (v0.w + v1.w) + (v2.w + v3.w);
    }
    for (; i < e; i++) {
        float4 v = yz[(size_t)csrc[i] * S4 + lane];
        acc.x += v.x; acc.y += v.y; acc.z += v.z; acc.w += v.w;
    }
    float inv = 1.0f / (float)max(e - s, 1);
    float4 z = yz[(size_t)node * S4 + C4 + lane];
    float4 bb = ((const float4*)b)[lane];
    float4 o;
    o.x = acc.x * inv + z.x + bb.x;
    o.y = acc.y * inv + z.y + bb.y;
    o.z = acc.z * inv + z.z + bb.z;
    o.w = acc.w * inv + z.w + bb.w;
    if (RELU) {
        o.x = fmaxf(o.x, 0.f); o.y = fmaxf(o.y, 0.f);
        o.z = fmaxf(o.z, 0.f); o.w = fmaxf(o.w, 0.f);
        o = round_tf32_4(o);   // next GEMM input: RNA-round here (free)
    }
    out[(size_t)node * C4 + lane] = o;
}

// ---------------------------------------------------------------------------
extern "C" void kernel_launch(void* const* d_in, const int* in_sizes, int n_in,
                              void* d_out, int out_size) {
    const float* x   = (const float*)d_in[0];
    const int*   ei  = (const int*)d_in[1];
    const float* Wl0 = (const float*)d_in[2];
    const float* Wr0 = (const float*)d_in[3];
    const float* b0  = (const float*)d_in[4];
    const float* Wl1 = (const float*)d_in[5];
    const float* Wr1 = (const float*)d_in[6];
    const float* b1  = (const float*)d_in[7];
    const float* Wl2 = (const float*)d_in[8];
    const float* Wr2 = (const float*)d_in[9];
    const float* b2  = (const float*)d_in[10];
    float* out = (float*)d_out;

    const int* src = ei;
    const int* dst = ei + NE;

    float *xr, *yz, *h, *wcat;
    int *cnt, *offs, *cursor, *csrc, *bsum;
    cudaGetSymbolAddress((void**)&xr,     g_x);
    cudaGetSymbolAddress((void**)&yz,     g_yz);
    cudaGetSymbolAddress((void**)&h,      g_h);
    cudaGetSymbolAddress((void**)&wcat,   g_wcat);
    cudaGetSymbolAddress((void**)&cnt,    g_cnt);
    cudaGetSymbolAddress((void**)&offs,   g_offs);
    cudaGetSymbolAddress((void**)&cursor, g_cursor);
    cudaGetSymbolAddress((void**)&csrc,   g_csrc);
    cudaGetSymbolAddress((void**)&bsum,   g_bsum);

    const int T = 256;

    dim3 gM(2, NN_PAD / 128);    // N = 256
    dim3 gM1(1, NN_PAD / 128);   // N = 128

    // ---- pre-round inputs; layer-0 GEMM is the 4th launch (ncu window) ----
    cvt_x<<<(NN_PAD * 32 + T - 1) / T, T>>>((const float4*)x, (float4*)xr); // 1
    cvt_w<<<(2 * 4096 + T - 1) / T, T>>>((const float4*)Wl0,
                                         (const float4*)Wr0,
                                         (float4*)wcat, 4096);              // 2
    zero_cnt<<<(NN + T - 1) / T, T>>>(cnt);                                 // 3
    tf32gemm<<<gM, T>>>(xr, wcat, yz, 256);                                 // 4

    // ---- CSR build ----
    count_deg<<<(NE + T - 1) / T, T>>>(dst, cnt);
    scan_a<<<NBLK, SCAN_B>>>(cnt, offs, bsum);
    scan_b<<<1, 128>>>(bsum);
    scan_c<<<(NN + T - 1) / T, T>>>(offs, bsum, cursor);
    place_edges<<<(NE + T - 1) / T, T>>>(src, dst, cursor, csrc);

    // ---- layer 0 combine ----
    agg_combine<32, true><<<(NN_PAD * 32 + T - 1) / T, T>>>(
        (const float4*)yz, csrc, offs, b0, (float4*)h);

    // ---- layer 1 ----
    cvt_w<<<(2 * 4096 + T - 1) / T, T>>>((const float4*)Wl1,
                                         (const float4*)Wr1,
                                         (float4*)wcat, 4096);
    tf32gemm<<<gM, T>>>(h, wcat, yz, 256);
    agg_combine<32, true><<<(NN_PAD * 32 + T - 1) / T, T>>>(
        (const float4*)yz, csrc, offs, b1, (float4*)h);

    // ---- layer 2 (d_out = 64, no relu, fp32 out) ----
    cvt_w<<<(2 * 2048 + T - 1) / T, T>>>((const float4*)Wl2,
                                         (const float4*)Wr2,
                                         (float4*)wcat, 2048);
    tf32gemm<<<gM1, T>>>(h, wcat, yz, 128);
    agg_combine<16, false><<<(NN * 16 + T - 1) / T, T>>>(
        (const float4*)yz, csrc, offs, b2, (float4*)out);
}

// round 9
// speedup vs baseline: 1.4392x; 1.4392x over previous
#include <cuda_runtime.h>
#include <mma.h>
#include <cstddef>
#include <cstdint>

using namespace nvcuda;

#define NN 100000
#define NN_PAD 100096            // 782 * 128
#define NE 1600000
#define SCAN_B 1024
#define NBLK ((NN + SCAN_B - 1) / SCAN_B)   // 98

// ---------------- scratch ---------------------------------------------------
__device__ float g_x[(size_t)NN_PAD * 128];  // tf32-rounded input x (padded)
__device__ float g_yz[(size_t)NN_PAD * 256];
__device__ float g_h[(size_t)NN_PAD * 128];  // tf32-rounded activations (padded)
__device__ float g_wcat[3][256 * 128];       // tf32-rounded [Wl ; Wr] per layer
__device__ int   g_cnt[NN];
__device__ int   g_offs[NN + 1];
__device__ int   g_cursor[NN];
__device__ int   g_csrc[NE];
__device__ int   g_bsum[NBLK];

// ---------------- helpers ---------------------------------------------------
__device__ __forceinline__ float4 round_tf32_4(float4 v) {
    return make_float4(wmma::__float_to_tf32(v.x), wmma::__float_to_tf32(v.y),
                       wmma::__float_to_tf32(v.z), wmma::__float_to_tf32(v.w));
}
__device__ __forceinline__ uint32_t smem_u32(const void* p) {
    return (uint32_t)__cvta_generic_to_shared(p);
}
#define CPA(dst, src) \
    asm volatile("cp.async.cg.shared.global [%0], [%1], 16;" :: "r"(dst), "l"(src))
#define CPC() asm volatile("cp.async.commit_group;")
#define CPW(n) asm volatile("cp.async.wait_group %0;" :: "n"(n))

// ---------------- CSR build -------------------------------------------------
__global__ void count_deg(const int* __restrict__ dst, int* __restrict__ cnt) {
    int e = blockIdx.x * blockDim.x + threadIdx.x;
    if (e < NE) atomicAdd(cnt + dst[e], 1);
}
__global__ void zero_cnt(int* __restrict__ cnt) {
    int i = blockIdx.x * blockDim.x + threadIdx.x;
    if (i < NN) cnt[i] = 0;
}
__global__ void scan_a(const int* __restrict__ cnt, int* __restrict__ offs,
                       int* __restrict__ bsum) {
    __shared__ int sh[SCAN_B];
    int gid = blockIdx.x * SCAN_B + threadIdx.x;
    int v = (gid < NN) ? cnt[gid] : 0;
    sh[threadIdx.x] = v;
    __syncthreads();
    for (int d = 1; d < SCAN_B; d <<= 1) {
        int t = (threadIdx.x >= d) ? sh[threadIdx.x - d] : 0;
        __syncthreads();
        sh[threadIdx.x] += t;
        __syncthreads();
    }
    if (gid < NN) offs[gid] = sh[threadIdx.x] - v;
    if (threadIdx.x == SCAN_B - 1) bsum[blockIdx.x] = sh[threadIdx.x];
}
__global__ void scan_b(int* __restrict__ bsum) {
    __shared__ int sh[128];
    int v = (threadIdx.x < NBLK) ? bsum[threadIdx.x] : 0;
    sh[threadIdx.x] = v;
    __syncthreads();
    for (int d = 1; d < 128; d <<= 1) {
        int t = (threadIdx.x >= d) ? sh[threadIdx.x - d] : 0;
        __syncthreads();
        sh[threadIdx.x] += t;
        __syncthreads();
    }
    if (threadIdx.x < NBLK) bsum[threadIdx.x] = sh[threadIdx.x] - v;
}
__global__ void scan_c(int* __restrict__ offs, const int* __restrict__ bsum,
                       int* __restrict__ cursor) {
    int gid = blockIdx.x * blockDim.x + threadIdx.x;
    if (gid < NN) {
        int o = offs[gid] + bsum[gid >> 10];
        offs[gid] = o;
        cursor[gid] = o;
    }
    if (gid == 0) offs[NN] = NE;
}
__global__ void place_edges(const int* __restrict__ src, const int* __restrict__ dst,
                            int* __restrict__ cursor, int* __restrict__ csrc) {
    int e = blockIdx.x * blockDim.x + threadIdx.x;
    if (e < NE) {
        int p = atomicAdd(cursor + dst[e], 1);
        csrc[p] = src[e];
    }
}

// ---------------- tf32 pre-rounding ----------------------------------------
__global__ void cvt_x(const float4* __restrict__ in, float4* __restrict__ out) {
    int i = blockIdx.x * blockDim.x + threadIdx.x;
    if (i >= NN_PAD * 32) return;
    float4 v = (i < NN * 32) ? in[i] : make_float4(0.f, 0.f, 0.f, 0.f);
    out[i] = round_tf32_4(v);
}
__global__ void cvt_w(const float4* __restrict__ Wl, const float4* __restrict__ Wr,
                      float4* __restrict__ out, int n4half) {
    int i = blockIdx.x * blockDim.x + threadIdx.x;
    if (i < n4half) out[i] = round_tf32_4(Wl[i]);
    else if (i < 2 * n4half) out[i] = round_tf32_4(Wr[i - n4half]);
}

// ---------------- TF32 tensor-core GEMM (verified R5 version) ---------------
// C[NN_PAD, N] = A[NN_PAD,128] * B[N,128]^T. A,B pre-rounded to tf32, padded.
// Block 128x128, BK=16, 8 warps (4x2), warp tile 32x64. cp.async 2-stage.
#define LDT 20

__global__ __launch_bounds__(256, 2) void tf32gemm(
    const float* __restrict__ A, const float* __restrict__ B,
    float* __restrict__ C, int N) {
    __shared__ float As[2][128][LDT];
    __shared__ float Bs[2][128][LDT];

    const int tid = threadIdx.x;
    const int warp = tid >> 5;
    const int wm = warp & 3;      // m offset 32*wm
    const int wn = warp >> 2;     // n offset 64*wn
    const int bm0 = blockIdx.y * 128;
    const int bn0 = blockIdx.x * 128;

    wmma::fragment<wmma::accumulator, 16, 16, 8, float> acc[2][4];
    #pragma unroll
    for (int i = 0; i < 2; i++)
        #pragma unroll
        for (int j = 0; j < 4; j++)
            wmma::fill_fragment(acc[i][j], 0.0f);

    // Loaders: per stage A,B each 128x16 floats = 512 float4; 2+2 per thread.
    const int f0 = tid * 2;
    const int r0 = f0 >> 2,       c0 = (f0 & 3) * 4;
    const int r1 = (f0 + 1) >> 2, c1 = ((f0 + 1) & 3) * 4;
    const float* A0 = A + (size_t)(bm0 + r0) * 128 + c0;
    const float* A1 = A + (size_t)(bm0 + r1) * 128 + c1;
    const float* B0 = B + (size_t)(bn0 + r0) * 128 + c0;
    const float* B1 = B + (size_t)(bn0 + r1) * 128 + c1;

    const uint32_t sA0 = smem_u32(&As[0][r0][c0]);
    const uint32_t sA1 = smem_u32(&As[0][r1][c1]);
    const uint32_t sB0 = smem_u32(&Bs[0][r0][c0]);
    const uint32_t sB1 = smem_u32(&Bs[0][r1][c1]);
    const uint32_t STG = 128 * LDT * 4;   // stage stride in bytes

    CPA(sA0, A0); CPA(sA1, A1); CPA(sB0, B0); CPA(sB1, B1); CPC();

    #pragma unroll
    for (int t = 0; t < 8; t++) {
        const int cur = t & 1;
        if (t < 7) {
            const uint32_t so = ((t + 1) & 1) * STG;
            const int k0 = (t + 1) * 16;
            CPA(sA0 + so, A0 + k0); CPA(sA1 + so, A1 + k0);
            CPA(sB0 + so, B0 + k0); CPA(sB1 + so, B1 + k0);
            CPC();
            CPW(1);
        } else {
            CPW(0);
        }
        __syncthreads();

        #pragma unroll
        for (int kk = 0; kk < 16; kk += 8) {
            wmma::fragment<wmma::matrix_a, 16, 16, 8, wmma::precision::tf32,
                           wmma::row_major> af[2];
            wmma::fragment<wmma::matrix_b, 16, 16, 8, wmma::precision::tf32,
                           wmma::col_major> bf[4];
            wmma::load_matrix_sync(af[0], &As[cur][wm * 32 + 0][kk], LDT);
            wmma::load_matrix_sync(af[1], &As[cur][wm * 32 + 16][kk], LDT);
            #pragma unroll
            for (int j = 0; j < 4; j++)
                wmma::load_matrix_sync(bf[j], &Bs[cur][wn * 64 + j * 16][kk], LDT);
            #pragma unroll
            for (int i = 0; i < 2; i++)
                #pragma unroll
                for (int j = 0; j < 4; j++)
                    wmma::mma_sync(acc[i][j], af[i], bf[j], acc[i][j]);
        }
        __syncthreads();   // protect stage 'cur' before iter t+1 overwrites it
    }

    #pragma unroll
    for (int i = 0; i < 2; i++)
        #pragma unroll
        for (int j = 0; j < 4; j++) {
            int row0 = bm0 + wm * 32 + i * 16;
            int col0 = bn0 + wn * 64 + j * 16;
            wmma::store_matrix_sync(C + (size_t)row0 * N + col0, acc[i][j], N,
                                    wmma::mem_row_major);
        }
}

// ---------------- fused aggregate + combine ---------------------------------
// out = [relu]( mean_{j in CSR[i]} y_j + z_i + b ). When RELU (layers 0/1):
// output is tf32-rounded (feeds next GEMM) and pad rows [NN,NN_PAD) are zeroed.
template <int C4, bool RELU>
__global__ void agg_combine(const float4* __restrict__ yz,
                            const int* __restrict__ csrc,
                            const int* __restrict__ offs,
                            const float* __restrict__ b,
                            float4* __restrict__ out) {
    const int S4 = 2 * C4;
    int gid = blockIdx.x * blockDim.x + threadIdx.x;
    int node = gid / C4;
    int lane = gid % C4;
    if (RELU) {
        if (node >= NN_PAD) return;
        if (node >= NN) {
            out[(size_t)node * C4 + lane] = make_float4(0.f, 0.f, 0.f, 0.f);
            return;
        }
    } else {
        if (node >= NN) return;
    }

    int s = offs[node], e = offs[node + 1];
    float4 acc = make_float4(0.f, 0.f, 0.f, 0.f);
    int i = s;
    for (; i + 3 < e; i += 4) {
        int s0 = csrc[i], s1 = csrc[i + 1], s2 = csrc[i + 2], s3 = csrc[i + 3];
        float4 v0 = yz[(size_t)s0 * S4 + lane];
        float4 v1 = yz[(size_t)s1 * S4 + lane];
        float4 v2 = yz[(size_t)s2 * S4 + lane];
        float4 v3 = yz[(size_t)s3 * S4 + lane];
        acc.x += (v0.x + v1.x) + (v2.x + v3.x);
        acc.y += (v0.y + v1.y) + (v2.y + v3.y);
        acc.z += (v0.z + v1.z) + (v2.z + v3.z);
        acc.w += (v0.w + v1.w) + (v2.w + v3.w);
    }
    for (; i < e; i++) {
        float4 v = yz[(size_t)csrc[i] * S4 + lane];
        acc.x += v.x; acc.y += v.y; acc.z += v.z; acc.w += v.w;
    }
    float inv = 1.0f / (float)max(e - s, 1);
    float4 z = yz[(size_t)node * S4 + C4 + lane];
    float4 bb = ((const float4*)b)[lane];
    float4 o;
    o.x = acc.x * inv + z.x + bb.x;
    o.y = acc.y * inv + z.y + bb.y;
    o.z = acc.z * inv + z.z + bb.z;
    o.w = acc.w * inv + z.w + bb.w;
    if (RELU) {
        o.x = fmaxf(o.x, 0.f); o.y = fmaxf(o.y, 0.f);
        o.z = fmaxf(o.z, 0.f); o.w = fmaxf(o.w, 0.f);
        o = round_tf32_4(o);   // next GEMM input: RNA-round here (free)
    }
    out[(size_t)node * C4 + lane] = o;
}

// ---------------------------------------------------------------------------
extern "C" void kernel_launch(void* const* d_in, const int* in_sizes, int n_in,
                              void* d_out, int out_size) {
    const float* x   = (const float*)d_in[0];
    const int*   ei  = (const int*)d_in[1];
    const float* Wl0 = (const float*)d_in[2];
    const float* Wr0 = (const float*)d_in[3];
    const float* b0  = (const float*)d_in[4];
    const float* Wl1 = (const float*)d_in[5];
    const float* Wr1 = (const float*)d_in[6];
    const float* b1  = (const float*)d_in[7];
    const float* Wl2 = (const float*)d_in[8];
    const float* Wr2 = (const float*)d_in[9];
    const float* b2  = (const float*)d_in[10];
    float* out = (float*)d_out;

    const int* src = ei;
    const int* dst = ei + NE;

    float *xr, *yz, *h, *wc;
    int *cnt, *offs, *cursor, *csrc, *bsum;
    cudaGetSymbolAddress((void**)&xr,     g_x);
    cudaGetSymbolAddress((void**)&yz,     g_yz);
    cudaGetSymbolAddress((void**)&h,      g_h);
    cudaGetSymbolAddress((void**)&wc,     g_wcat);
    cudaGetSymbolAddress((void**)&cnt,    g_cnt);
    cudaGetSymbolAddress((void**)&offs,   g_offs);
    cudaGetSymbolAddress((void**)&cursor, g_cursor);
    cudaGetSymbolAddress((void**)&csrc,   g_csrc);
    cudaGetSymbolAddress((void**)&bsum,   g_bsum);
    float* wc0 = wc;
    float* wc1 = wc + 256 * 128;
    float* wc2 = wc + 2 * 256 * 128;

    const int T = 256;
    dim3 gM(2, NN_PAD / 128);    // N = 256
    dim3 gM1(1, NN_PAD / 128);   // N = 128

    // Side stream for the CSR build + weight conversions (fork/join pattern,
    // graph-capture safe). kernel_launch runs exactly twice (correctness +
    // capture), so unconditional creation leaks nothing meaningful and keeps
    // every call identical.
    cudaStream_t s2;
    cudaEvent_t evFork, evJoin;
    cudaStreamCreateWithFlags(&s2, cudaStreamNonBlocking);
    cudaEventCreateWithFlags(&evFork, cudaEventDisableTiming);
    cudaEventCreateWithFlags(&evJoin, cudaEventDisableTiming);

    cudaEventRecord(evFork, 0);
    cudaStreamWaitEvent(s2, evFork, 0);

    // ---- main stream: tf32 input prep + layer-0 GEMM (4th kernel launch) ----
    cvt_x<<<(NN_PAD * 32 + T - 1) / T, T>>>((const float4*)x, (float4*)xr); // 1
    cvt_w<<<(2 * 4096 + T - 1) / T, T>>>((const float4*)Wl0,
                                         (const float4*)Wr0,
                                         (float4*)wc0, 4096);               // 2
    zero_cnt<<<(NN + T - 1) / T, T, 0, s2>>>(cnt);                          // 3 (s2)
    tf32gemm<<<gM, T>>>(xr, wc0, yz, 256);                                  // 4 <- ncu

    // ---- side stream: CSR build + remaining weight conversions ----
    count_deg<<<(NE + T - 1) / T, T, 0, s2>>>(dst, cnt);
    scan_a<<<NBLK, SCAN_B, 0, s2>>>(cnt, offs, bsum);
    scan_b<<<1, 128, 0, s2>>>(bsum);
    scan_c<<<(NN + T - 1) / T, T, 0, s2>>>(offs, bsum, cursor);
    place_edges<<<(NE + T - 1) / T, T, 0, s2>>>(src, dst, cursor, csrc);
    cvt_w<<<(2 * 4096 + T - 1) / T, T, 0, s2>>>((const float4*)Wl1,
                                                (const float4*)Wr1,
                                                (float4*)wc1, 4096);
    cvt_w<<<(2 * 2048 + T - 1) / T, T, 0, s2>>>((const float4*)Wl2,
                                                (const float4*)Wr2,
                                                (float4*)wc2, 2048);
    cudaEventRecord(evJoin, s2);
    cudaStreamWaitEvent(0, evJoin, 0);

    // ---- layer 0 combine ----
    agg_combine<32, true><<<(NN_PAD * 32 + T - 1) / T, T>>>(
        (const float4*)yz, csrc, offs, b0, (float4*)h);

    // ---- layer 1 ----
    tf32gemm<<<gM, T>>>(h, wc1, yz, 256);
    agg_combine<32, true><<<(NN_PAD * 32 + T - 1) / T, T>>>(
        (const float4*)yz, csrc, offs, b1, (float4*)h);

    // ---- layer 2 (d_out = 64, no relu, fp32 out) ----
    tf32gemm<<<gM1, T>>>(h, wc2, yz, 128);
    agg_combine<16, false><<<(NN * 16 + T - 1) / T, T>>>(
        (const float4*)yz, csrc, offs, b2, (float4*)out);
}

// round 10
// speedup vs baseline: 1.4700x; 1.0214x over previous
#include <cuda_runtime.h>
#include <mma.h>
#include <cstddef>
#include <cstdint>

using namespace nvcuda;

#define NN 100000
#define NN_PAD 100096            // 782 * 128
#define NE 1600000
#define SCAN_B 1024
#define NBLK ((NN + SCAN_B - 1) / SCAN_B)   // 98

// ---------------- scratch ---------------------------------------------------
__device__ float g_y[(size_t)NN_PAD * 128];  // y = h@Wl^T (gathered over edges)
__device__ float g_z[(size_t)NN_PAD * 128];  // z = h@Wr^T (streamed per node)
__device__ float g_h[(size_t)NN_PAD * 128];  // tf32-rounded activations (padded)
__device__ float g_wcat[3][256 * 128];       // tf32-rounded [Wl ; Wr] per layer
__device__ int   g_cnt[NN];
__device__ int   g_offs[NN + 1];
__device__ int   g_cursor[NN];
__device__ int   g_csrc[NE];
__device__ int   g_bsum[NBLK];

// ---------------- helpers ---------------------------------------------------
__device__ __forceinline__ float4 round_tf32_4(float4 v) {
    return make_float4(wmma::__float_to_tf32(v.x), wmma::__float_to_tf32(v.y),
                       wmma::__float_to_tf32(v.z), wmma::__float_to_tf32(v.w));
}
__device__ __forceinline__ uint32_t smem_u32(const void* p) {
    return (uint32_t)__cvta_generic_to_shared(p);
}
#define CPA(dst, src) \
    asm volatile("cp.async.cg.shared.global [%0], [%1], 16;" :: "r"(dst), "l"(src))
#define CPA_Z(dst, src, sz) \
    asm volatile("cp.async.cg.shared.global [%0], [%1], 16, %2;" \
                 :: "r"(dst), "l"(src), "r"(sz))
#define CPC() asm volatile("cp.async.commit_group;")
#define CPW(n) asm volatile("cp.async.wait_group %0;" :: "n"(n))

// ---------------- CSR build -------------------------------------------------
__global__ void count_deg(const int* __restrict__ dst, int* __restrict__ cnt) {
    int e = blockIdx.x * blockDim.x + threadIdx.x;
    if (e < NE) atomicAdd(cnt + dst[e], 1);
}
__global__ void zero_cnt(int* __restrict__ cnt) {
    int i = blockIdx.x * blockDim.x + threadIdx.x;
    if (i < NN) cnt[i] = 0;
}
__global__ void scan_a(const int* __restrict__ cnt, int* __restrict__ offs,
                       int* __restrict__ bsum) {
    __shared__ int sh[SCAN_B];
    int gid = blockIdx.x * SCAN_B + threadIdx.x;
    int v = (gid < NN) ? cnt[gid] : 0;
    sh[threadIdx.x] = v;
    __syncthreads();
    for (int d = 1; d < SCAN_B; d <<= 1) {
        int t = (threadIdx.x >= d) ? sh[threadIdx.x - d] : 0;
        __syncthreads();
        sh[threadIdx.x] += t;
        __syncthreads();
    }
    if (gid < NN) offs[gid] = sh[threadIdx.x] - v;
    if (threadIdx.x == SCAN_B - 1) bsum[blockIdx.x] = sh[threadIdx.x];
}
__global__ void scan_b(int* __restrict__ bsum) {
    __shared__ int sh[128];
    int v = (threadIdx.x < NBLK) ? bsum[threadIdx.x] : 0;
    sh[threadIdx.x] = v;
    __syncthreads();
    for (int d = 1; d < 128; d <<= 1) {
        int t = (threadIdx.x >= d) ? sh[threadIdx.x - d] : 0;
        __syncthreads();
        sh[threadIdx.x] += t;
        __syncthreads();
    }
    if (threadIdx.x < NBLK) bsum[threadIdx.x] = sh[threadIdx.x] - v;
}
__global__ void scan_c(int* __restrict__ offs, const int* __restrict__ bsum,
                       int* __restrict__ cursor) {
    int gid = blockIdx.x * blockDim.x + threadIdx.x;
    if (gid < NN) {
        int o = offs[gid] + bsum[gid >> 10];
        offs[gid] = o;
        cursor[gid] = o;
    }
    if (gid == 0) offs[NN] = NE;
}
__global__ void place_edges(const int* __restrict__ src, const int* __restrict__ dst,
                            int* __restrict__ cursor, int* __restrict__ csrc) {
    int e = blockIdx.x * blockDim.x + threadIdx.x;
    if (e < NE) {
        int p = atomicAdd(cursor + dst[e], 1);
        csrc[p] = src[e];
    }
}

// ---------------- tf32 weight pre-rounding ----------------------------------
__global__ void cvt_w(const float4* __restrict__ Wl, const float4* __restrict__ Wr,
                      float4* __restrict__ out, int n4half) {
    int i = blockIdx.x * blockDim.x + threadIdx.x;
    if (i < n4half) out[i] = round_tf32_4(Wl[i]);
    else if (i < 2 * n4half) out[i] = round_tf32_4(Wr[i - n4half]);
}

// ---------------- TF32 tensor-core GEMM, split Y/Z epilogue ------------------
// [Y|Z][NN_PAD, N/2 each] = A[M,128] * B[N,128]^T, B = [Wl;Wr] concat.
// Block 128x128, BK=16, 8 warps (4x2), warp tile 32x64, cp.async 2-stage.
// A rows >= M are zero-filled via cp.async src-size guard (pad rows -> C=0).
// Warp slab (64 cols) is entirely Y (slab < N/2) or entirely Z.
#define LDT 20

__global__ __launch_bounds__(256, 2) void tf32gemm(
    const float* __restrict__ A, const float* __restrict__ B,
    float* __restrict__ Y, float* __restrict__ Z, int M, int N) {
    __shared__ float As[2][128][LDT];
    __shared__ float Bs[2][128][LDT];

    const int tid = threadIdx.x;
    const int warp = tid >> 5;
    const int wm = warp & 3;      // m offset 32*wm
    const int wn = warp >> 2;     // n offset 64*wn
    const int bm0 = blockIdx.y * 128;
    const int bn0 = blockIdx.x * 128;

    wmma::fragment<wmma::accumulator, 16, 16, 8, float> acc[2][4];
    #pragma unroll
    for (int i = 0; i < 2; i++)
        #pragma unroll
        for (int j = 0; j < 4; j++)
            wmma::fill_fragment(acc[i][j], 0.0f);

    // Loaders: per stage A,B each 128x16 floats = 512 float4; 2+2 per thread.
    const int f0 = tid * 2;
    const int r0 = f0 >> 2,       c0 = (f0 & 3) * 4;
    const int r1 = (f0 + 1) >> 2, c1 = ((f0 + 1) & 3) * 4;
    const bool ok0 = (bm0 + r0) < M;
    const bool ok1 = (bm0 + r1) < M;
    const uint32_t sz0 = ok0 ? 16u : 0u;
    const uint32_t sz1 = ok1 ? 16u : 0u;
    const float* A0 = A + (size_t)(ok0 ? bm0 + r0 : 0) * 128 + c0;
    const float* A1 = A + (size_t)(ok1 ? bm0 + r1 : 0) * 128 + c1;
    const float* B0 = B + (size_t)(bn0 + r0) * 128 + c0;
    const float* B1 = B + (size_t)(bn0 + r1) * 128 + c1;

    const uint32_t sA0 = smem_u32(&As[0][r0][c0]);
    const uint32_t sA1 = smem_u32(&As[0][r1][c1]);
    const uint32_t sB0 = smem_u32(&Bs[0][r0][c0]);
    const uint32_t sB1 = smem_u32(&Bs[0][r1][c1]);
    const uint32_t STG = 128 * LDT * 4;   // stage stride in bytes

    CPA_Z(sA0, A0, sz0); CPA_Z(sA1, A1, sz1);
    CPA(sB0, B0); CPA(sB1, B1); CPC();

    #pragma unroll
    for (int t = 0; t < 8; t++) {
        const int cur = t & 1;
        if (t < 7) {
            const uint32_t so = ((t + 1) & 1) * STG;
            const int k0 = (t + 1) * 16;
            CPA_Z(sA0 + so, A0 + k0, sz0); CPA_Z(sA1 + so, A1 + k0, sz1);
            CPA(sB0 + so, B0 + k0); CPA(sB1 + so, B1 + k0);
            CPC();
            CPW(1);
        } else {
            CPW(0);
        }
        __syncthreads();

        #pragma unroll
        for (int kk = 0; kk < 16; kk += 8) {
            wmma::fragment<wmma::matrix_a, 16, 16, 8, wmma::precision::tf32,
                           wmma::row_major> af[2];
            wmma::fragment<wmma::matrix_b, 16, 16, 8, wmma::precision::tf32,
                           wmma::col_major> bf[4];
            wmma::load_matrix_sync(af[0], &As[cur][wm * 32 + 0][kk], LDT);
            wmma::load_matrix_sync(af[1], &As[cur][wm * 32 + 16][kk], LDT);
            #pragma unroll
            for (int j = 0; j < 4; j++)
                wmma::load_matrix_sync(bf[j], &Bs[cur][wn * 64 + j * 16][kk], LDT);
            #pragma unroll
            for (int i = 0; i < 2; i++)
                #pragma unroll
                for (int j = 0; j < 4; j++)
                    wmma::mma_sync(acc[i][j], af[i], bf[j], acc[i][j]);
        }
        __syncthreads();   // protect stage 'cur' before iter t+1 overwrites it
    }

    // Split epilogue: identical store pattern, base pointer per warp slab.
    const int halfN = N >> 1;
    const int slab0 = bn0 + wn * 64;
    float* Cb = (slab0 < halfN) ? Y : Z;
    const int ccol = (slab0 < halfN) ? slab0 : slab0 - halfN;
    #pragma unroll
    for (int i = 0; i < 2; i++)
        #pragma unroll
        for (int j = 0; j < 4; j++) {
            int row0 = bm0 + wm * 32 + i * 16;
            wmma::store_matrix_sync(Cb + (size_t)row0 * halfN + ccol + j * 16,
                                    acc[i][j], halfN, wmma::mem_row_major);
        }
}

// ---------------- fused aggregate + combine ---------------------------------
// out = [relu]( mean_{j in CSR[i]} y_j + z_i + b ); y compact (L2-resident),
// z streamed. When RELU: output tf32-rounded, pad rows zeroed.
template <int C4, bool RELU>
__global__ void agg_combine(const float4* __restrict__ y4,
                            const float4* __restrict__ z4,
                            const int* __restrict__ csrc,
                            const int* __restrict__ offs,
                            const float* __restrict__ b,
                            float4* __restrict__ out) {
    int gid = blockIdx.x * blockDim.x + threadIdx.x;
    int node = gid / C4;
    int lane = gid % C4;
    if (RELU) {
        if (node >= NN_PAD) return;
        if (node >= NN) {
            out[(size_t)node * C4 + lane] = make_float4(0.f, 0.f, 0.f, 0.f);
            return;
        }
    } else {
        if (node >= NN) return;
    }

    int s = offs[node], e = offs[node + 1];
    float4 acc = make_float4(0.f, 0.f, 0.f, 0.f);
    int i = s;
    for (; i + 3 < e; i += 4) {
        int s0 = csrc[i], s1 = csrc[i + 1], s2 = csrc[i + 2], s3 = csrc[i + 3];
        float4 v0 = y4[(size_t)s0 * C4 + lane];
        float4 v1 = y4[(size_t)s1 * C4 + lane];
        float4 v2 = y4[(size_t)s2 * C4 + lane];
        float4 v3 = y4[(size_t)s3 * C4 + lane];
        acc.x += (v0.x + v1.x) + (v2.x + v3.x);
        acc.y += (v0.y + v1.y) + (v2.y + v3.y);
        acc.z += (v0.z + v1.z) + (v2.z + v3.z);
        acc.w += (v0.w + v1.w) + (v2.w + v3.w);
    }
    for (; i < e; i++) {
        float4 v = y4[(size_t)csrc[i] * C4 + lane];
        acc.x += v.x; acc.y += v.y; acc.z += v.z; acc.w += v.w;
    }
    float inv = 1.0f / (float)max(e - s, 1);
    float4 z = z4[(size_t)node * C4 + lane];
    float4 bb = ((const float4*)b)[lane];
    float4 o;
    o.x = acc.x * inv + z.x + bb.x;
    o.y = acc.y * inv + z.y + bb.y;
    o.z = acc.z * inv + z.z + bb.z;
    o.w = acc.w * inv + z.w + bb.w;
    if (RELU) {
        o.x = fmaxf(o.x, 0.f); o.y = fmaxf(o.y, 0.f);
        o.z = fmaxf(o.z, 0.f); o.w = fmaxf(o.w, 0.f);
        o = round_tf32_4(o);   // next GEMM input: RNA-round here (free)
    }
    out[(size_t)node * C4 + lane] = o;
}

// ---------------------------------------------------------------------------
extern "C" void kernel_launch(void* const* d_in, const int* in_sizes, int n_in,
                              void* d_out, int out_size) {
    const float* x   = (const float*)d_in[0];
    const int*   ei  = (const int*)d_in[1];
    const float* Wl0 = (const float*)d_in[2];
    const float* Wr0 = (const float*)d_in[3];
    const float* b0  = (const float*)d_in[4];
    const float* Wl1 = (const float*)d_in[5];
    const float* Wr1 = (const float*)d_in[6];
    const float* b1  = (const float*)d_in[7];
    const float* Wl2 = (const float*)d_in[8];
    const float* Wr2 = (const float*)d_in[9];
    const float* b2  = (const float*)d_in[10];
    float* out = (float*)d_out;

    const int* src = ei;
    const int* dst = ei + NE;

    float *y, *z, *h, *wc;
    int *cnt, *offs, *cursor, *csrc, *bsum;
    cudaGetSymbolAddress((void**)&y,      g_y);
    cudaGetSymbolAddress((void**)&z,      g_z);
    cudaGetSymbolAddress((void**)&h,      g_h);
    cudaGetSymbolAddress((void**)&wc,     g_wcat);
    cudaGetSymbolAddress((void**)&cnt,    g_cnt);
    cudaGetSymbolAddress((void**)&offs,   g_offs);
    cudaGetSymbolAddress((void**)&cursor, g_cursor);
    cudaGetSymbolAddress((void**)&csrc,   g_csrc);
    cudaGetSymbolAddress((void**)&bsum,   g_bsum);
    float* wc0 = wc;
    float* wc1 = wc + 256 * 128;
    float* wc2 = wc + 2 * 256 * 128;

    const int T = 256;
    dim3 gM(2, NN_PAD / 128);    // N = 256
    dim3 gM1(1, NN_PAD / 128);   // N = 128

    // Fork/join side stream (verified R9 pattern).
    cudaStream_t s2;
    cudaEvent_t evFork, evJoin;
    cudaStreamCreateWithFlags(&s2, cudaStreamNonBlocking);
    cudaEventCreateWithFlags(&evFork, cudaEventDisableTiming);
    cudaEventCreateWithFlags(&evJoin, cudaEventDisableTiming);

    cudaEventRecord(evFork, 0);
    cudaStreamWaitEvent(s2, evFork, 0);

    // ---- main: weight prep + layer-0 GEMM (4th kernel launch for ncu) ----
    cvt_w<<<(2 * 4096 + T - 1) / T, T>>>((const float4*)Wl0,
                                         (const float4*)Wr0,
                                         (float4*)wc0, 4096);               // 1
    zero_cnt<<<(NN + T - 1) / T, T, 0, s2>>>(cnt);                          // 2 (s2)
    count_deg<<<(NE + T - 1) / T, T, 0, s2>>>(dst, cnt);                    // 3 (s2)
    tf32gemm<<<gM, T>>>(x, wc0, y, z, NN, 256);                             // 4 <- ncu

    // ---- side stream: CSR build + remaining weight conversions ----
    scan_a<<<NBLK, SCAN_B, 0, s2>>>(cnt, offs, bsum);
    scan_b<<<1, 128, 0, s2>>>(bsum);
    scan_c<<<(NN + T - 1) / T, T, 0, s2>>>(offs, bsum, cursor);
    place_edges<<<(NE + T - 1) / T, T, 0, s2>>>(src, dst, cursor, csrc);
    cvt_w<<<(2 * 4096 + T - 1) / T, T, 0, s2>>>((const float4*)Wl1,
                                                (const float4*)Wr1,
                                                (float4*)wc1, 4096);
    cvt_w<<<(2 * 2048 + T - 1) / T, T, 0, s2>>>((const float4*)Wl2,
                                                (const float4*)Wr2,
                                                (float4*)wc2, 2048);
    cudaEventRecord(evJoin, s2);
    cudaStreamWaitEvent(0, evJoin, 0);

    // ---- layer 0 combine ----
    agg_combine<32, true><<<(NN_PAD * 32 + T - 1) / T, T>>>(
        (const float4*)y, (const float4*)z, csrc, offs, b0, (float4*)h);

    // ---- layer 1 ----
    tf32gemm<<<gM, T>>>(h, wc1, y, z, NN_PAD, 256);
    agg_combine<32, true><<<(NN_PAD * 32 + T - 1) / T, T>>>(
        (const float4*)y, (const float4*)z, csrc, offs, b1, (float4*)h);

    // ---- layer 2 (d_out = 64, no relu, fp32 out) ----
    tf32gemm<<<gM1, T>>>(h, wc2, y, z, NN_PAD, 128);
    agg_combine<16, false><<<(NN * 16 + T - 1) / T, T>>>(
        (const float4*)y, (const float4*)z, csrc, offs, b2, (float4*)out);
}

// round 11
// speedup vs baseline: 1.5395x; 1.0473x over previous
#include <cuda_runtime.h>
#include <mma.h>
#include <cuda_fp16.h>
#include <cstddef>
#include <cstdint>

using namespace nvcuda;

#define NN 100000
#define NN_PAD 100096            // 782 * 128
#define NE 1600000
#define SCAN_B 1024
#define NBLK ((NN + SCAN_B - 1) / SCAN_B)   // 98

// ---------------- scratch ---------------------------------------------------
__device__ float  g_y[(size_t)NN_PAD * 128];  // y = h@Wl^T fp32 (GEMM out)
__device__ __half g_yh[(size_t)NN * 128];     // y in fp16 (gathered over edges)
__device__ float  g_z[(size_t)NN_PAD * 128];  // z = h@Wr^T (streamed per node)
__device__ float  g_h[(size_t)NN_PAD * 128];  // tf32-rounded activations
__device__ float  g_wcat[3][256 * 128];       // tf32-rounded [Wl ; Wr] per layer
__device__ int    g_cnt[NN];
__device__ int    g_offs[NN + 1];
__device__ int    g_cursor[NN];
__device__ int    g_csrc[NE];
__device__ int    g_bsum[NBLK];

// ---------------- helpers ---------------------------------------------------
__device__ __forceinline__ float4 round_tf32_4(float4 v) {
    return make_float4(wmma::__float_to_tf32(v.x), wmma::__float_to_tf32(v.y),
                       wmma::__float_to_tf32(v.z), wmma::__float_to_tf32(v.w));
}
__device__ __forceinline__ uint32_t smem_u32(const void* p) {
    return (uint32_t)__cvta_generic_to_shared(p);
}
#define CPA(dst, src) \
    asm volatile("cp.async.cg.shared.global [%0], [%1], 16;" :: "r"(dst), "l"(src))
#define CPA_Z(dst, src, sz) \
    asm volatile("cp.async.cg.shared.global [%0], [%1], 16, %2;" \
                 :: "r"(dst), "l"(src), "r"(sz))
#define CPC() asm volatile("cp.async.commit_group;")
#define CPW(n) asm volatile("cp.async.wait_group %0;" :: "n"(n))

// ---------------- CSR build -------------------------------------------------
__global__ void count_deg(const int* __restrict__ dst, int* __restrict__ cnt) {
    int e = blockIdx.x * blockDim.x + threadIdx.x;
    if (e < NE) atomicAdd(cnt + dst[e], 1);
}
__global__ void zero_cnt(int* __restrict__ cnt) {
    int i = blockIdx.x * blockDim.x + threadIdx.x;
    if (i < NN) cnt[i] = 0;
}
__global__ void scan_a(const int* __restrict__ cnt, int* __restrict__ offs,
                       int* __restrict__ bsum) {
    __shared__ int sh[SCAN_B];
    int gid = blockIdx.x * SCAN_B + threadIdx.x;
    int v = (gid < NN) ? cnt[gid] : 0;
    sh[threadIdx.x] = v;
    __syncthreads();
    for (int d = 1; d < SCAN_B; d <<= 1) {
        int t = (threadIdx.x >= d) ? sh[threadIdx.x - d] : 0;
        __syncthreads();
        sh[threadIdx.x] += t;
        __syncthreads();
    }
    if (gid < NN) offs[gid] = sh[threadIdx.x] - v;
    if (threadIdx.x == SCAN_B - 1) bsum[blockIdx.x] = sh[threadIdx.x];
}
__global__ void scan_b(int* __restrict__ bsum) {
    __shared__ int sh[128];
    int v = (threadIdx.x < NBLK) ? bsum[threadIdx.x] : 0;
    sh[threadIdx.x] = v;
    __syncthreads();
    for (int d = 1; d < 128; d <<= 1) {
        int t = (threadIdx.x >= d) ? sh[threadIdx.x - d] : 0;
        __syncthreads();
        sh[threadIdx.x] += t;
        __syncthreads();
    }
    if (threadIdx.x < NBLK) bsum[threadIdx.x] = sh[threadIdx.x] - v;
}
__global__ void scan_c(int* __restrict__ offs, const int* __restrict__ bsum,
                       int* __restrict__ cursor) {
    int gid = blockIdx.x * blockDim.x + threadIdx.x;
    if (gid < NN) {
        int o = offs[gid] + bsum[gid >> 10];
        offs[gid] = o;
        cursor[gid] = o;
    }
    if (gid == 0) offs[NN] = NE;
}
__global__ void place_edges(const int* __restrict__ src, const int* __restrict__ dst,
                            int* __restrict__ cursor, int* __restrict__ csrc) {
    int e = blockIdx.x * blockDim.x + threadIdx.x;
    if (e < NE) {
        int p = atomicAdd(cursor + dst[e], 1);
        csrc[p] = src[e];
    }
}

// ---------------- tf32 weight pre-rounding ----------------------------------
__global__ void cvt_w(const float4* __restrict__ Wl, const float4* __restrict__ Wr,
                      float4* __restrict__ out, int n4half) {
    int i = blockIdx.x * blockDim.x + threadIdx.x;
    if (i < n4half) out[i] = round_tf32_4(Wl[i]);
    else if (i < 2 * n4half) out[i] = round_tf32_4(Wr[i - n4half]);
}

// ---------------- y fp32 -> fp16 (coalesced streaming) ----------------------
// Each thread: 8 floats (2 float4) -> 1 uint4 of 8 halves. n = rows*cols/8.
__global__ void cvt_y(const float4* __restrict__ in, uint4* __restrict__ out,
                      int n) {
    int i = blockIdx.x * blockDim.x + threadIdx.x;
    if (i >= n) return;
    float4 f0 = in[2 * i], f1 = in[2 * i + 1];
    union { uint4 u; __half2 h[4]; } P;
    P.h[0] = __floats2half2_rn(f0.x, f0.y);
    P.h[1] = __floats2half2_rn(f0.z, f0.w);
    P.h[2] = __floats2half2_rn(f1.x, f1.y);
    P.h[3] = __floats2half2_rn(f1.z, f1.w);
    out[i] = P.u;
}

// ---------------- TF32 tensor-core GEMM, split Y/Z epilogue ------------------
// (verified R10 version — untouched)
#define LDT 20

__global__ __launch_bounds__(256, 2) void tf32gemm(
    const float* __restrict__ A, const float* __restrict__ B,
    float* __restrict__ Y, float* __restrict__ Z, int M, int N) {
    __shared__ float As[2][128][LDT];
    __shared__ float Bs[2][128][LDT];

    const int tid = threadIdx.x;
    const int warp = tid >> 5;
    const int wm = warp & 3;
    const int wn = warp >> 2;
    const int bm0 = blockIdx.y * 128;
    const int bn0 = blockIdx.x * 128;

    wmma::fragment<wmma::accumulator, 16, 16, 8, float> acc[2][4];
    #pragma unroll
    for (int i = 0; i < 2; i++)
        #pragma unroll
        for (int j = 0; j < 4; j++)
            wmma::fill_fragment(acc[i][j], 0.0f);

    const int f0 = tid * 2;
    const int r0 = f0 >> 2,       c0 = (f0 & 3) * 4;
    const int r1 = (f0 + 1) >> 2, c1 = ((f0 + 1) & 3) * 4;
    const bool ok0 = (bm0 + r0) < M;
    const bool ok1 = (bm0 + r1) < M;
    const uint32_t sz0 = ok0 ? 16u : 0u;
    const uint32_t sz1 = ok1 ? 16u : 0u;
    const float* A0 = A + (size_t)(ok0 ? bm0 + r0 : 0) * 128 + c0;
    const float* A1 = A + (size_t)(ok1 ? bm0 + r1 : 0) * 128 + c1;
    const float* B0 = B + (size_t)(bn0 + r0) * 128 + c0;
    const float* B1 = B + (size_t)(bn0 + r1) * 128 + c1;

    const uint32_t sA0 = smem_u32(&As[0][r0][c0]);
    const uint32_t sA1 = smem_u32(&As[0][r1][c1]);
    const uint32_t sB0 = smem_u32(&Bs[0][r0][c0]);
    const uint32_t sB1 = smem_u32(&Bs[0][r1][c1]);
    const uint32_t STG = 128 * LDT * 4;

    CPA_Z(sA0, A0, sz0); CPA_Z(sA1, A1, sz1);
    CPA(sB0, B0); CPA(sB1, B1); CPC();

    #pragma unroll
    for (int t = 0; t < 8; t++) {
        const int cur = t & 1;
        if (t < 7) {
            const uint32_t so = ((t + 1) & 1) * STG;
            const int k0 = (t + 1) * 16;
            CPA_Z(sA0 + so, A0 + k0, sz0); CPA_Z(sA1 + so, A1 + k0, sz1);
            CPA(sB0 + so, B0 + k0); CPA(sB1 + so, B1 + k0);
            CPC();
            CPW(1);
        } else {
            CPW(0);
        }
        __syncthreads();

        #pragma unroll
        for (int kk = 0; kk < 16; kk += 8) {
            wmma::fragment<wmma::matrix_a, 16, 16, 8, wmma::precision::tf32,
                           wmma::row_major> af[2];
            wmma::fragment<wmma::matrix_b, 16, 16, 8, wmma::precision::tf32,
                           wmma::col_major> bf[4];
            wmma::load_matrix_sync(af[0], &As[cur][wm * 32 + 0][kk], LDT);
            wmma::load_matrix_sync(af[1], &As[cur][wm * 32 + 16][kk], LDT);
            #pragma unroll
            for (int j = 0; j < 4; j++)
                wmma::load_matrix_sync(bf[j], &Bs[cur][wn * 64 + j * 16][kk], LDT);
            #pragma unroll
            for (int i = 0; i < 2; i++)
                #pragma unroll
                for (int j = 0; j < 4; j++)
                    wmma::mma_sync(acc[i][j], af[i], bf[j], acc[i][j]);
        }
        __syncthreads();
    }

    const int halfN = N >> 1;
    const int slab0 = bn0 + wn * 64;
    float* Cb = (slab0 < halfN) ? Y : Z;
    const int ccol = (slab0 < halfN) ? slab0 : slab0 - halfN;
    #pragma unroll
    for (int i = 0; i < 2; i++)
        #pragma unroll
        for (int j = 0; j < 4; j++) {
            int row0 = bm0 + wm * 32 + i * 16;
            wmma::store_matrix_sync(Cb + (size_t)row0 * halfN + ccol + j * 16,
                                    acc[i][j], halfN, wmma::mem_row_major);
        }
}

// ---------------- fused aggregate + combine (fp16 y gather) ------------------
// out = [relu]( mean_{j in CSR[i]} y_j + z_i + b ); y fp16 (halved gather
// bytes), fp32 accumulate; z/out fp32. HL lanes per node, 8 cols per lane.
template <int HL, bool RELU>
__global__ void agg_combine(const uint4* __restrict__ yh4,
                            const float4* __restrict__ z4,
                            const int* __restrict__ csrc,
                            const int* __restrict__ offs,
                            const float* __restrict__ b,
                            float4* __restrict__ out) {
    int gid = blockIdx.x * blockDim.x + threadIdx.x;
    int node = gid / HL;
    int lane = gid % HL;
    if (RELU) {
        if (node >= NN_PAD) return;
        if (node >= NN) {
            float4 zf = make_float4(0.f, 0.f, 0.f, 0.f);
            out[(size_t)node * 2 * HL + lane * 2 + 0] = zf;
            out[(size_t)node * 2 * HL + lane * 2 + 1] = zf;
            return;
        }
    } else {
        if (node >= NN) return;
    }

    int s = offs[node], e = offs[node + 1];
    float a[8] = {0.f, 0.f, 0.f, 0.f, 0.f, 0.f, 0.f, 0.f};
    int i = s;
    for (; i + 1 < e; i += 2) {
        uint4 u0 = yh4[(size_t)csrc[i] * HL + lane];
        uint4 u1 = yh4[(size_t)csrc[i + 1] * HL + lane];
        const __half2* p0 = (const __half2*)&u0;
        const __half2* p1 = (const __half2*)&u1;
        #pragma unroll
        for (int k = 0; k < 4; k++) {
            float2 f0 = __half22float2(p0[k]);
            float2 f1 = __half22float2(p1[k]);
            a[2 * k]     += f0.x + f1.x;
            a[2 * k + 1] += f0.y + f1.y;
        }
    }
    if (i < e) {
        uint4 u = yh4[(size_t)csrc[i] * HL + lane];
        const __half2* p = (const __half2*)&u;
        #pragma unroll
        for (int k = 0; k < 4; k++) {
            float2 f = __half22float2(p[k]);
            a[2 * k]     += f.x;
            a[2 * k + 1] += f.y;
        }
    }

    float inv = 1.0f / (float)max(e - s, 1);
    float4 z0 = z4[(size_t)node * 2 * HL + lane * 2 + 0];
    float4 z1 = z4[(size_t)node * 2 * HL + lane * 2 + 1];
    float4 bb0 = ((const float4*)b)[lane * 2 + 0];
    float4 bb1 = ((const float4*)b)[lane * 2 + 1];
    float4 o0, o1;
    o0.x = a[0] * inv + z0.x + bb0.x;
    o0.y = a[1] * inv + z0.y + bb0.y;
    o0.z = a[2] * inv + z0.z + bb0.z;
    o0.w = a[3] * inv + z0.w + bb0.w;
    o1.x = a[4] * inv + z1.x + bb1.x;
    o1.y = a[5] * inv + z1.y + bb1.y;
    o1.z = a[6] * inv + z1.z + bb1.z;
    o1.w = a[7] * inv + z1.w + bb1.w;
    if (RELU) {
        o0.x = fmaxf(o0.x, 0.f); o0.y = fmaxf(o0.y, 0.f);
        o0.z = fmaxf(o0.z, 0.f); o0.w = fmaxf(o0.w, 0.f);
        o1.x = fmaxf(o1.x, 0.f); o1.y = fmaxf(o1.y, 0.f);
        o1.z = fmaxf(o1.z, 0.f); o1.w = fmaxf(o1.w, 0.f);
        o0 = round_tf32_4(o0);   // next GEMM input
        o1 = round_tf32_4(o1);
    }
    out[(size_t)node * 2 * HL + lane * 2 + 0] = o0;
    out[(size_t)node * 2 * HL + lane * 2 + 1] = o1;
}

// ---------------------------------------------------------------------------
extern "C" void kernel_launch(void* const* d_in, const int* in_sizes, int n_in,
                              void* d_out, int out_size) {
    const float* x   = (const float*)d_in[0];
    const int*   ei  = (const int*)d_in[1];
    const float* Wl0 = (const float*)d_in[2];
    const float* Wr0 = (const float*)d_in[3];
    const float* b0  = (const float*)d_in[4];
    const float* Wl1 = (const float*)d_in[5];
    const float* Wr1 = (const float*)d_in[6];
    const float* b1  = (const float*)d_in[7];
    const float* Wl2 = (const float*)d_in[8];
    const float* Wr2 = (const float*)d_in[9];
    const float* b2  = (const float*)d_in[10];
    float* out = (float*)d_out;

    const int* src = ei;
    const int* dst = ei + NE;

    float *y, *z, *h, *wc;
    __half* yh;
    int *cnt, *offs, *cursor, *csrc, *bsum;
    cudaGetSymbolAddress((void**)&y,      g_y);
    cudaGetSymbolAddress((void**)&yh,     g_yh);
    cudaGetSymbolAddress((void**)&z,      g_z);
    cudaGetSymbolAddress((void**)&h,      g_h);
    cudaGetSymbolAddress((void**)&wc,     g_wcat);
    cudaGetSymbolAddress((void**)&cnt,    g_cnt);
    cudaGetSymbolAddress((void**)&offs,   g_offs);
    cudaGetSymbolAddress((void**)&cursor, g_cursor);
    cudaGetSymbolAddress((void**)&csrc,   g_csrc);
    cudaGetSymbolAddress((void**)&bsum,   g_bsum);
    float* wc0 = wc;
    float* wc1 = wc + 256 * 128;
    float* wc2 = wc + 2 * 256 * 128;

    const int T = 256;
    dim3 gM(2, NN_PAD / 128);    // N = 256
    dim3 gM1(1, NN_PAD / 128);   // N = 128

    // Fork/join side stream (verified R9 pattern).
    cudaStream_t s2;
    cudaEvent_t evFork, evJoin;
    cudaStreamCreateWithFlags(&s2, cudaStreamNonBlocking);
    cudaEventCreateWithFlags(&evFork, cudaEventDisableTiming);
    cudaEventCreateWithFlags(&evJoin, cudaEventDisableTiming);

    cudaEventRecord(evFork, 0);
    cudaStreamWaitEvent(s2, evFork, 0);

    // ---- main: weight prep + layer-0 GEMM (4th kernel launch for ncu) ----
    cvt_w<<<(2 * 4096 + T - 1) / T, T>>>((const float4*)Wl0,
                                         (const float4*)Wr0,
                                         (float4*)wc0, 4096);               // 1
    zero_cnt<<<(NN + T - 1) / T, T, 0, s2>>>(cnt);                          // 2 (s2)
    count_deg<<<(NE + T - 1) / T, T, 0, s2>>>(dst, cnt);                    // 3 (s2)
    tf32gemm<<<gM, T>>>(x, wc0, y, z, NN, 256);                             // 4 <- ncu
    cvt_y<<<(NN * 16 + T - 1) / T, T>>>((const float4*)y, (uint4*)yh, NN * 16);

    // ---- side stream: CSR build + remaining weight conversions ----
    scan_a<<<NBLK, SCAN_B, 0, s2>>>(cnt, offs, bsum);
    scan_b<<<1, 128, 0, s2>>>(bsum);
    scan_c<<<(NN + T - 1) / T, T, 0, s2>>>(offs, bsum, cursor);
    place_edges<<<(NE + T - 1) / T, T, 0, s2>>>(src, dst, cursor, csrc);
    cvt_w<<<(2 * 4096 + T - 1) / T, T, 0, s2>>>((const float4*)Wl1,
                                                (const float4*)Wr1,
                                                (float4*)wc1, 4096);
    cvt_w<<<(2 * 2048 + T - 1) / T, T, 0, s2>>>((const float4*)Wl2,
                                                (const float4*)Wr2,
                                                (float4*)wc2, 2048);
    cudaEventRecord(evJoin, s2);
    cudaStreamWaitEvent(0, evJoin, 0);

    // ---- layer 0 combine ----
    agg_combine<16, true><<<(NN_PAD * 16 + T - 1) / T, T>>>(
        (const uint4*)yh, (const float4*)z, csrc, offs, b0, (float4*)h);

    // ---- layer 1 ----
    tf32gemm<<<gM, T>>>(h, wc1, y, z, NN_PAD, 256);
    cvt_y<<<(NN * 16 + T - 1) / T, T>>>((const float4*)y, (uint4*)yh, NN * 16);
    agg_combine<16, true><<<(NN_PAD * 16 + T - 1) / T, T>>>(
        (const uint4*)yh, (const float4*)z, csrc, offs, b1, (float4*)h);

    // ---- layer 2 (d_out = 64, no relu, fp32 out) ----
    tf32gemm<<<gM1, T>>>(h, wc2, y, z, NN_PAD, 128);
    cvt_y<<<(NN * 8 + T - 1) / T, T>>>((const float4*)y, (uint4*)yh, NN * 8);
    agg_combine<8, false><<<(NN * 8 + T - 1) / T, T>>>(
        (const uint4*)yh, (const float4*)z, csrc, offs, b2, (float4*)out);
}

// round 12
// speedup vs baseline: 2.4497x; 1.5912x over previous
#include <cuda_runtime.h>
#include <mma.h>
#include <cuda_fp16.h>
#include <cstddef>
#include <cstdint>

using namespace nvcuda;

#define NN 100000
#define NN_PAD 100096            // 782 * 128
#define NE 1600000
#define SCAN_B 1024
#define NBLK ((NN + SCAN_B - 1) / SCAN_B)   // 98

// ---------------- scratch ---------------------------------------------------
__device__ __half g_x[(size_t)NN_PAD * 128];   // x in fp16 (padded, zeroed)
__device__ float  g_y[(size_t)NN_PAD * 128];   // y = h@Wl^T fp32 (GEMM out)
__device__ __half g_yh[(size_t)NN * 128];      // y fp16 (gathered over edges)
__device__ float  g_z[(size_t)NN_PAD * 128];   // z = h@Wr^T fp32
__device__ __half g_h[(size_t)NN_PAD * 128];   // activations fp16 (padded)
__device__ __half g_wcat[3][256 * 128];        // fp16 [Wl ; Wr] per layer
__device__ int    g_cnt[NN];
__device__ int    g_offs[NN + 1];
__device__ int    g_cursor[NN];
__device__ int    g_csrc[NE];
__device__ int    g_bsum[NBLK];

// ---------------- helpers ---------------------------------------------------
__device__ __forceinline__ uint4 pack8h(float4 f0, float4 f1) {
    union { uint4 u; __half2 h[4]; } P;
    P.h[0] = __floats2half2_rn(f0.x, f0.y);
    P.h[1] = __floats2half2_rn(f0.z, f0.w);
    P.h[2] = __floats2half2_rn(f1.x, f1.y);
    P.h[3] = __floats2half2_rn(f1.z, f1.w);
    return P.u;
}
__device__ __forceinline__ uint32_t smem_u32(const void* p) {
    return (uint32_t)__cvta_generic_to_shared(p);
}
#define CPA(dst, src) \
    asm volatile("cp.async.cg.shared.global [%0], [%1], 16;" :: "r"(dst), "l"(src))
#define CPC() asm volatile("cp.async.commit_group;")
#define CPW(n) asm volatile("cp.async.wait_group %0;" :: "n"(n))

// ---------------- CSR build -------------------------------------------------
__global__ void count_deg(const int* __restrict__ dst, int* __restrict__ cnt) {
    int e = blockIdx.x * blockDim.x + threadIdx.x;
    if (e < NE) atomicAdd(cnt + dst[e], 1);
}
__global__ void zero_cnt(int* __restrict__ cnt) {
    int i = blockIdx.x * blockDim.x + threadIdx.x;
    if (i < NN) cnt[i] = 0;
}
__global__ void scan_a(const int* __restrict__ cnt, int* __restrict__ offs,
                       int* __restrict__ bsum) {
    __shared__ int sh[SCAN_B];
    int gid = blockIdx.x * SCAN_B + threadIdx.x;
    int v = (gid < NN) ? cnt[gid] : 0;
    sh[threadIdx.x] = v;
    __syncthreads();
    for (int d = 1; d < SCAN_B; d <<= 1) {
        int t = (threadIdx.x >= d) ? sh[threadIdx.x - d] : 0;
        __syncthreads();
        sh[threadIdx.x] += t;
        __syncthreads();
    }
    if (gid < NN) offs[gid] = sh[threadIdx.x] - v;
    if (threadIdx.x == SCAN_B - 1) bsum[blockIdx.x] = sh[threadIdx.x];
}
__global__ void scan_b(int* __restrict__ bsum) {
    __shared__ int sh[128];
    int v = (threadIdx.x < NBLK) ? bsum[threadIdx.x] : 0;
    sh[threadIdx.x] = v;
    __syncthreads();
    for (int d = 1; d < 128; d <<= 1) {
        int t = (threadIdx.x >= d) ? sh[threadIdx.x - d] : 0;
        __syncthreads();
        sh[threadIdx.x] += t;
        __syncthreads();
    }
    if (threadIdx.x < NBLK) bsum[threadIdx.x] = sh[threadIdx.x] - v;
}
__global__ void scan_c(int* __restrict__ offs, const int* __restrict__ bsum,
                       int* __restrict__ cursor) {
    int gid = blockIdx.x * blockDim.x + threadIdx.x;
    if (gid < NN) {
        int o = offs[gid] + bsum[gid >> 10];
        offs[gid] = o;
        cursor[gid] = o;
    }
    if (gid == 0) offs[NN] = NE;
}
__global__ void place_edges(const int* __restrict__ src, const int* __restrict__ dst,
                            int* __restrict__ cursor, int* __restrict__ csrc) {
    int e = blockIdx.x * blockDim.x + threadIdx.x;
    if (e < NE) {
        int p = atomicAdd(cursor + dst[e], 1);
        csrc[p] = src[e];
    }
}

// ---------------- fp16 conversions -------------------------------------------
// x (fp32, NN rows) -> fp16 padded buffer (pad rows zero). n runs over NN_PAD*16.
__global__ void cvt_x_h(const float4* __restrict__ in, uint4* __restrict__ out) {
    int i = blockIdx.x * blockDim.x + threadIdx.x;
    if (i >= NN_PAD * 16) return;
    uint4 u = make_uint4(0u, 0u, 0u, 0u);
    if (i < NN * 16) u = pack8h(in[2 * i], in[2 * i + 1]);
    out[i] = u;
}
// [Wl ; Wr] fp32 -> fp16 concat. n8half = rows*128/8 per half-matrix.
__global__ void cvt_w_h(const float4* __restrict__ Wl, const float4* __restrict__ Wr,
                        uint4* __restrict__ out, int n8half) {
    int i = blockIdx.x * blockDim.x + threadIdx.x;
    if (i < n8half)
        out[i] = pack8h(Wl[2 * i], Wl[2 * i + 1]);
    else if (i < 2 * n8half) {
        int j = i - n8half;
        out[i] = pack8h(Wr[2 * j], Wr[2 * j + 1]);
    }
}
// y fp32 -> fp16 (coalesced streaming), n = rows*cols/8.
__global__ void cvt_y(const float4* __restrict__ in, uint4* __restrict__ out,
                      int n) {
    int i = blockIdx.x * blockDim.x + threadIdx.x;
    if (i >= n) return;
    out[i] = pack8h(in[2 * i], in[2 * i + 1]);
}

// ---------------- FP16 tensor-core GEMM, split Y/Z epilogue ------------------
// [Y|Z][M, N/2 each fp32] = A[M,128] * B[N,128]^T, A,B fp16, B = [Wl;Wr].
// Block 128x128, BK=16, 8 warps (4x2), warp tile 32x64, cp.async 2-stage.
// Structure identical to the proven tf32 kernel; one m16n16k16 mma per k-iter.
// A buffers are padded+zeroed to NN_PAD rows -> no guards anywhere.
#define LDTH 24   // halves per smem row (48 B stride; conflict-free ldmatrix)

__global__ __launch_bounds__(256, 2) void h16gemm(
    const __half* __restrict__ A, const __half* __restrict__ B,
    float* __restrict__ Y, float* __restrict__ Z, int N) {
    __shared__ __half As[2][128][LDTH];
    __shared__ __half Bs[2][128][LDTH];

    const int tid = threadIdx.x;
    const int warp = tid >> 5;
    const int wm = warp & 3;      // m offset 32*wm
    const int wn = warp >> 2;     // n offset 64*wn
    const int bm0 = blockIdx.y * 128;
    const int bn0 = blockIdx.x * 128;

    wmma::fragment<wmma::accumulator, 16, 16, 16, float> acc[2][4];
    #pragma unroll
    for (int i = 0; i < 2; i++)
        #pragma unroll
        for (int j = 0; j < 4; j++)
            wmma::fill_fragment(acc[i][j], 0.0f);

    // Loaders: per stage A,B each 128x16 halves = 4096 B; 256 threads x 16 B.
    const int r = tid >> 1;            // row 0..127
    const int c = (tid & 1) * 8;       // half-col 0 or 8
    const __half* Ap = A + (size_t)(bm0 + r) * 128 + c;
    const __half* Bp = B + (size_t)(bn0 + r) * 128 + c;

    const uint32_t sA = smem_u32(&As[0][r][c]);
    const uint32_t sB = smem_u32(&Bs[0][r][c]);
    const uint32_t STG = 128 * LDTH * 2;   // stage stride in bytes

    CPA(sA, Ap); CPA(sB, Bp); CPC();

    #pragma unroll
    for (int t = 0; t < 8; t++) {
        const int cur = t & 1;
        if (t < 7) {
            const uint32_t so = ((t + 1) & 1) * STG;
            const int k0 = (t + 1) * 16;
            CPA(sA + so, Ap + k0);
            CPA(sB + so, Bp + k0);
            CPC();
            CPW(1);
        } else {
            CPW(0);
        }
        __syncthreads();

        wmma::fragment<wmma::matrix_a, 16, 16, 16, __half, wmma::row_major> af[2];
        wmma::fragment<wmma::matrix_b, 16, 16, 16, __half, wmma::col_major> bf[4];
        wmma::load_matrix_sync(af[0], &As[cur][wm * 32 + 0][0], LDTH);
        wmma::load_matrix_sync(af[1], &As[cur][wm * 32 + 16][0], LDTH);
        #pragma unroll
        for (int j = 0; j < 4; j++)
            wmma::load_matrix_sync(bf[j], &Bs[cur][wn * 64 + j * 16][0], LDTH);
        #pragma unroll
        for (int i = 0; i < 2; i++)
            #pragma unroll
            for (int j = 0; j < 4; j++)
                wmma::mma_sync(acc[i][j], af[i], bf[j], acc[i][j]);

        __syncthreads();   // protect stage 'cur' before iter t+1 overwrites it
    }

    // Split epilogue: identical store pattern, base pointer per warp slab.
    const int halfN = N >> 1;
    const int slab0 = bn0 + wn * 64;
    float* Cb = (slab0 < halfN) ? Y : Z;
    const int ccol = (slab0 < halfN) ? slab0 : slab0 - halfN;
    #pragma unroll
    for (int i = 0; i < 2; i++)
        #pragma unroll
        for (int j = 0; j < 4; j++) {
            int row0 = bm0 + wm * 32 + i * 16;
            wmma::store_matrix_sync(Cb + (size_t)row0 * halfN + ccol + j * 16,
                                    acc[i][j], halfN, wmma::mem_row_major);
        }
}

// ---------------- fused aggregate + combine (fp16 y gather) ------------------
// out = [relu]( mean_{j in CSR[i]} y_j + z_i + b ); y fp16, fp32 accumulate.
// RELU layers write fp16 h (pad rows zeroed); final layer writes fp32 out.
template <int HL, bool RELU>
__global__ void agg_combine(const uint4* __restrict__ yh4,
                            const float4* __restrict__ z4,
                            const int* __restrict__ csrc,
                            const int* __restrict__ offs,
                            const float* __restrict__ b,
                            uint4* __restrict__ outh,
                            float4* __restrict__ outf) {
    int gid = blockIdx.x * blockDim.x + threadIdx.x;
    int node = gid / HL;
    int lane = gid % HL;
    if (RELU) {
        if (node >= NN_PAD) return;
        if (node >= NN) {
            outh[(size_t)node * HL + lane] = make_uint4(0u, 0u, 0u, 0u);
            return;
        }
    } else {
        if (node >= NN) return;
    }

    int s = offs[node], e = offs[node + 1];
    float a[8] = {0.f, 0.f, 0.f, 0.f, 0.f, 0.f, 0.f, 0.f};
    int i = s;
    for (; i + 1 < e; i += 2) {
        uint4 u0 = yh4[(size_t)csrc[i] * HL + lane];
        uint4 u1 = yh4[(size_t)csrc[i + 1] * HL + lane];
        const __half2* p0 = (const __half2*)&u0;
        const __half2* p1 = (const __half2*)&u1;
        #pragma unroll
        for (int k = 0; k < 4; k++) {
            float2 f0 = __half22float2(p0[k]);
            float2 f1 = __half22float2(p1[k]);
            a[2 * k]     += f0.x + f1.x;
            a[2 * k + 1] += f0.y + f1.y;
        }
    }
    if (i < e) {
        uint4 u = yh4[(size_t)csrc[i] * HL + lane];
        const __half2* p = (const __half2*)&u;
        #pragma unroll
        for (int k = 0; k < 4; k++) {
            float2 f = __half22float2(p[k]);
            a[2 * k]     += f.x;
            a[2 * k + 1] += f.y;
        }
    }

    float inv = 1.0f / (float)max(e - s, 1);
    float4 z0 = z4[(size_t)node * 2 * HL + lane * 2 + 0];
    float4 z1 = z4[(size_t)node * 2 * HL + lane * 2 + 1];
    float4 bb0 = ((const float4*)b)[lane * 2 + 0];
    float4 bb1 = ((const float4*)b)[lane * 2 + 1];
    float4 o0, o1;
    o0.x = a[0] * inv + z0.x + bb0.x;
    o0.y = a[1] * inv + z0.y + bb0.y;
    o0.z = a[2] * inv + z0.z + bb0.z;
    o0.w = a[3] * inv + z0.w + bb0.w;
    o1.x = a[4] * inv + z1.x + bb1.x;
    o1.y = a[5] * inv + z1.y + bb1.y;
    o1.z = a[6] * inv + z1.z + bb1.z;
    o1.w = a[7] * inv + z1.w + bb1.w;
    if (RELU) {
        o0.x = fmaxf(o0.x, 0.f); o0.y = fmaxf(o0.y, 0.f);
        o0.z = fmaxf(o0.z, 0.f); o0.w = fmaxf(o0.w, 0.f);
        o1.x = fmaxf(o1.x, 0.f); o1.y = fmaxf(o1.y, 0.f);
        o1.z = fmaxf(o1.z, 0.f); o1.w = fmaxf(o1.w, 0.f);
        outh[(size_t)node * HL + lane] = pack8h(o0, o1);  // fp16 h (next GEMM A)
    } else {
        outf[(size_t)node * 2 * HL + lane * 2 + 0] = o0;
        outf[(size_t)node * 2 * HL + lane * 2 + 1] = o1;
    }
}

// ---------------------------------------------------------------------------
extern "C" void kernel_launch(void* const* d_in, const int* in_sizes, int n_in,
                              void* d_out, int out_size) {
    const float* x   = (const float*)d_in[0];
    const int*   ei  = (const int*)d_in[1];
    const float* Wl0 = (const float*)d_in[2];
    const float* Wr0 = (const float*)d_in[3];
    const float* b0  = (const float*)d_in[4];
    const float* Wl1 = (const float*)d_in[5];
    const float* Wr1 = (const float*)d_in[6];
    const float* b1  = (const float*)d_in[7];
    const float* Wl2 = (const float*)d_in[8];
    const float* Wr2 = (const float*)d_in[9];
    const float* b2  = (const float*)d_in[10];
    float* out = (float*)d_out;

    const int* src = ei;
    const int* dst = ei + NE;

    float *y, *z;
    __half *xh, *yh, *h, *wc;
    int *cnt, *offs, *cursor, *csrc, *bsum;
    cudaGetSymbolAddress((void**)&xh,     g_x);
    cudaGetSymbolAddress((void**)&y,      g_y);
    cudaGetSymbolAddress((void**)&yh,     g_yh);
    cudaGetSymbolAddress((void**)&z,      g_z);
    cudaGetSymbolAddress((void**)&h,      g_h);
    cudaGetSymbolAddress((void**)&wc,     g_wcat);
    cudaGetSymbolAddress((void**)&cnt,    g_cnt);
    cudaGetSymbolAddress((void**)&offs,   g_offs);
    cudaGetSymbolAddress((void**)&cursor, g_cursor);
    cudaGetSymbolAddress((void**)&csrc,   g_csrc);
    cudaGetSymbolAddress((void**)&bsum,   g_bsum);
    __half* wc0 = wc;
    __half* wc1 = wc + 256 * 128;
    __half* wc2 = wc + 2 * 256 * 128;

    const int T = 256;
    dim3 gM(2, NN_PAD / 128);    // N = 256
    dim3 gM1(1, NN_PAD / 128);   // N = 128

    // Fork/join side stream (verified R9 pattern).
    cudaStream_t s2;
    cudaEvent_t evFork, evJoin;
    cudaStreamCreateWithFlags(&s2, cudaStreamNonBlocking);
    cudaEventCreateWithFlags(&evFork, cudaEventDisableTiming);
    cudaEventCreateWithFlags(&evJoin, cudaEventDisableTiming);

    cudaEventRecord(evFork, 0);
    cudaStreamWaitEvent(s2, evFork, 0);

    // ---- main: fp16 input prep + layer-0 GEMM (4th kernel launch for ncu) ----
    cvt_x_h<<<(NN_PAD * 16 + T - 1) / T, T>>>((const float4*)x, (uint4*)xh); // 1
    cvt_w_h<<<(2 * 2048 + T - 1) / T, T>>>((const float4*)Wl0,
                                           (const float4*)Wr0,
                                           (uint4*)wc0, 2048);               // 2
    zero_cnt<<<(NN + T - 1) / T, T, 0, s2>>>(cnt);                           // 3 (s2)
    h16gemm<<<gM, T>>>(xh, wc0, y, z, 256);                                  // 4 <- ncu
    cvt_y<<<(NN * 16 + T - 1) / T, T>>>((const float4*)y, (uint4*)yh, NN * 16);

    // ---- side stream: CSR build + remaining weight conversions ----
    count_deg<<<(NE + T - 1) / T, T, 0, s2>>>(dst, cnt);
    scan_a<<<NBLK, SCAN_B, 0, s2>>>(cnt, offs, bsum);
    scan_b<<<1, 128, 0, s2>>>(bsum);
    scan_c<<<(NN + T - 1) / T, T, 0, s2>>>(offs, bsum, cursor);
    place_edges<<<(NE + T - 1) / T, T, 0, s2>>>(src, dst, cursor, csrc);
    cvt_w_h<<<(2 * 2048 + T - 1) / T, T, 0, s2>>>((const float4*)Wl1,
                                                  (const float4*)Wr1,
                                                  (uint4*)wc1, 2048);
    cvt_w_h<<<(2 * 1024 + T - 1) / T, T, 0, s2>>>((const float4*)Wl2,
                                                  (const float4*)Wr2,
                                                  (uint4*)wc2, 1024);
    cudaEventRecord(evJoin, s2);
    cudaStreamWaitEvent(0, evJoin, 0);

    // ---- layer 0 combine (writes fp16 h) ----
    agg_combine<16, true><<<(NN_PAD * 16 + T - 1) / T, T>>>(
        (const uint4*)yh, (const float4*)z, csrc, offs, b0, (uint4*)h, nullptr);

    // ---- layer 1 ----
    h16gemm<<<gM, T>>>(h, wc1, y, z, 256);
    cvt_y<<<(NN * 16 + T - 1) / T, T>>>((const float4*)y, (uint4*)yh, NN * 16);
    agg_combine<16, true><<<(NN_PAD * 16 + T - 1) / T, T>>>(
        (const uint4*)yh, (const float4*)z, csrc, offs, b1, (uint4*)h, nullptr);

    // ---- layer 2 (d_out = 64, no relu, fp32 out) ----
    h16gemm<<<gM1, T>>>(h, wc2, y, z, 128);
    cvt_y<<<(NN * 8 + T - 1) / T, T>>>((const float4*)y, (uint4*)yh, NN * 8);
    agg_combine<8, false><<<(NN * 8 + T - 1) / T, T>>>(
        (const uint4*)yh, (const float4*)z, csrc, offs, b2, nullptr, (float4*)out);
}